// round 1
// baseline (speedup 1.0000x reference)
#include <cuda_runtime.h>
#include <math.h>

// TransformationRotationLoss — streaming reduction over N rows of 3 fp32.
// loss[j] = mean_over_masked_rows( ALPHA*u_ta[j]^2 + BETTA*u_tb[j]^2 )
// with u_ta = sin(a)*(n2*s1 - n1*s2), u_tb = (cos(a)-1)*(n1*s1 + n2*s2),
// a = arccos(clip(n1·u2)).  We use sin(a)=sqrt(1-c^2), cos(a)-1 = c-1.

#define ALPHA 0.7f
#define BETTA 0.3f

static constexpr int THREADS    = 256;
static constexpr int MAX_BLOCKS = 2048;

__device__ float4 g_partials[MAX_BLOCKS];

__device__ __forceinline__ void process_row(
    float ax, float ay, float az,
    float bx, float by, float bz,
    float& sx, float& sy, float& sz, float& cnt)
{
    float r1sq = fmaf(ax, ax, fmaf(ay, ay, az * az));
    if (!(r1sq > 1e-16f)) return;   // mask: ||v1|| > 1e-8
    float r2sq = fmaf(bx, bx, fmaf(by, by, bz * bz));

    float inv1 = rsqrtf(r1sq);
    float inv2 = (r2sq > 0.0f) ? rsqrtf(r2sq) : 1.0f;

    float n1x = ax * inv1, n1y = ay * inv1, n1z = az * inv1;
    float u2x = bx * inv2, u2y = by * inv2, u2z = bz * inv2;

    float c = fmaf(n1x, u2x, fmaf(n1y, u2y, n1z * u2z));
    c = fminf(1.0f, fmaxf(-1.0f, c));

    // Gram-Schmidt: p = v2 - n1*(n1·v2), n2 = unit(p)
    float proj = fmaf(n1x, bx, fmaf(n1y, by, n1z * bz));
    float px = fmaf(-n1x, proj, bx);
    float py = fmaf(-n1y, proj, by);
    float pz = fmaf(-n1z, proj, bz);
    float psq = fmaf(px, px, fmaf(py, py, pz * pz));
    float invp = (psq > 0.0f) ? rsqrtf(psq) : 1.0f;
    float n2x = px * invp, n2y = py * invp, n2z = pz * invp;

    float sina = sqrtf(fmaxf(1.0f - c * c, 0.0f));
    float cm1  = c - 1.0f;

    float s1 = n1x + n1y + n1z;
    float s2 = n2x + n2y + n2z;

    float tax = sina * fmaf(n2x, s1, -n1x * s2);
    float tay = sina * fmaf(n2y, s1, -n1y * s2);
    float taz = sina * fmaf(n2z, s1, -n1z * s2);

    float tbx = cm1 * fmaf(n1x, s1, n2x * s2);
    float tby = cm1 * fmaf(n1y, s1, n2y * s2);
    float tbz = cm1 * fmaf(n1z, s1, n2z * s2);

    sx += fmaf(ALPHA, tax * tax, BETTA * tbx * tbx);
    sy += fmaf(ALPHA, tay * tay, BETTA * tby * tby);
    sz += fmaf(ALPHA, taz * taz, BETTA * tbz * tbz);
    cnt += 1.0f;
}

__device__ __forceinline__ void block_reduce_and_store(
    float sx, float sy, float sz, float cnt, float4* dst)
{
    // warp reduce
    #pragma unroll
    for (int o = 16; o > 0; o >>= 1) {
        sx  += __shfl_down_sync(0xffffffffu, sx,  o);
        sy  += __shfl_down_sync(0xffffffffu, sy,  o);
        sz  += __shfl_down_sync(0xffffffffu, sz,  o);
        cnt += __shfl_down_sync(0xffffffffu, cnt, o);
    }
    __shared__ float4 smem[THREADS / 32];
    int lane = threadIdx.x & 31;
    int warp = threadIdx.x >> 5;
    if (lane == 0) smem[warp] = make_float4(sx, sy, sz, cnt);
    __syncthreads();
    if (warp == 0) {
        float4 v = (lane < (blockDim.x >> 5)) ? smem[lane]
                                              : make_float4(0.f, 0.f, 0.f, 0.f);
        sx = v.x; sy = v.y; sz = v.z; cnt = v.w;
        #pragma unroll
        for (int o = 16; o > 0; o >>= 1) {
            sx  += __shfl_down_sync(0xffffffffu, sx,  o);
            sy  += __shfl_down_sync(0xffffffffu, sy,  o);
            sz  += __shfl_down_sync(0xffffffffu, sz,  o);
            cnt += __shfl_down_sync(0xffffffffu, cnt, o);
        }
        if (lane == 0) *dst = make_float4(sx, sy, sz, cnt);
    }
}

__global__ __launch_bounds__(THREADS)
void trl_reduce_kernel(const float* __restrict__ v1,
                       const float* __restrict__ v2,
                       int rows)
{
    float sx = 0.f, sy = 0.f, sz = 0.f, cnt = 0.f;

    const int tid    = blockIdx.x * blockDim.x + threadIdx.x;
    const int stride = gridDim.x * blockDim.x;
    const int rows4  = rows >> 2;            // groups of 4 rows = 3 float4 per input

    const float4* __restrict__ a4 = reinterpret_cast<const float4*>(v1);
    const float4* __restrict__ b4 = reinterpret_cast<const float4*>(v2);

    for (int g = tid; g < rows4; g += stride) {
        float4 a0 = a4[3 * g + 0];
        float4 a1 = a4[3 * g + 1];
        float4 a2 = a4[3 * g + 2];
        float4 b0 = b4[3 * g + 0];
        float4 b1 = b4[3 * g + 1];
        float4 b2 = b4[3 * g + 2];

        process_row(a0.x, a0.y, a0.z, b0.x, b0.y, b0.z, sx, sy, sz, cnt);
        process_row(a0.w, a1.x, a1.y, b0.w, b1.x, b1.y, sx, sy, sz, cnt);
        process_row(a1.z, a1.w, a2.x, b1.z, b1.w, b2.x, sx, sy, sz, cnt);
        process_row(a2.y, a2.z, a2.w, b2.y, b2.z, b2.w, sx, sy, sz, cnt);
    }
    // tail rows (rows % 4), scalar
    for (int r = (rows4 << 2) + tid; r < rows; r += stride) {
        process_row(v1[3 * r], v1[3 * r + 1], v1[3 * r + 2],
                    v2[3 * r], v2[3 * r + 1], v2[3 * r + 2],
                    sx, sy, sz, cnt);
    }

    block_reduce_and_store(sx, sy, sz, cnt, &g_partials[blockIdx.x]);
}

__device__ __forceinline__ float fix_num(float x) {
    if (isnan(x)) return 0.0f;
    if (isinf(x)) return x > 0.0f ? 0.1f : -0.1f;
    return x;
}

__global__ __launch_bounds__(THREADS)
void trl_finalize_kernel(float* __restrict__ out, int nblocks)
{
    float sx = 0.f, sy = 0.f, sz = 0.f, cnt = 0.f;
    for (int i = threadIdx.x; i < nblocks; i += blockDim.x) {
        float4 p = g_partials[i];
        sx += p.x; sy += p.y; sz += p.z; cnt += p.w;
    }
    __shared__ float4 result;
    block_reduce_and_store(sx, sy, sz, cnt, &result);
    __syncthreads();
    if (threadIdx.x == 0) {
        float inv = 1.0f / fmaxf(result.w, 1.0f);
        out[0] = fix_num(result.x * inv);
        out[1] = fix_num(result.y * inv);
        out[2] = fix_num(result.z * inv);
    }
}

extern "C" void kernel_launch(void* const* d_in, const int* in_sizes, int n_in,
                              void* d_out, int out_size)
{
    const float* v1 = (const float*)d_in[0];
    const float* v2 = (const float*)d_in[1];
    float* out = (float*)d_out;

    int rows  = in_sizes[0] / 3;
    int rows4 = rows >> 2;
    int blocks = (rows4 + THREADS - 1) / THREADS;
    if (blocks < 1) blocks = 1;
    if (blocks > MAX_BLOCKS) blocks = MAX_BLOCKS;

    trl_reduce_kernel<<<blocks, THREADS>>>(v1, v2, rows);
    trl_finalize_kernel<<<1, THREADS>>>(out, blocks);
}